// round 7
// baseline (speedup 1.0000x reference)
#include <cuda_runtime.h>
#include <cuda_fp16.h>
#include <cstdint>

#define Bsz 1024
#define Gdim 2048
#define Edim 256
#define Hdim 32
#define Vdim 14463
#define Vpad 14592   // 114 * 128
#define Tdim 18
#define Sdim 18      // last step's output is dropped
#define G4  128      // 4*H
#define Mtot (Bsz * Sdim)   // 18432
#define WCVT_BLOCKS 1824    // Vpad*32/256

// ---- scratch (no cudaMalloc allowed) ----
__device__ float g_init[Bsz * Edim];                       // graph projection
__device__ float g_gx0[Bsz * Sdim * G4];                   // L0 input-gates precompute
__device__ __align__(16) __half g_h2cv[Mtot * 32];         // h2 rows: fp16, 32/row
__device__ __align__(16) __half g_wcv[(size_t)Vpad * 32];  // Wout rows: fp16, 32/row

// ================= packed f32x2 helpers =================
static __device__ __forceinline__ unsigned long long pk2(float lo, float hi) {
    unsigned long long r;
    asm("mov.b64 %0, {%1,%2};" : "=l"(r) : "f"(lo), "f"(hi));
    return r;
}
static __device__ __forceinline__ unsigned long long fma2(unsigned long long a,
                                                          unsigned long long b,
                                                          unsigned long long c) {
    unsigned long long d;
    asm("fma.rn.f32x2 %0, %1, %2, %3;" : "=l"(d) : "l"(a), "l"(b), "l"(c));
    return d;
}
static __device__ __forceinline__ float2 up2(unsigned long long v) {
    float2 f;
    asm("mov.b64 {%0,%1}, %2;" : "=f"(f.x), "=f"(f.y) : "l"(v));
    return f;
}
static __device__ __forceinline__ float sigf(float x) {
    return 1.0f / (1.0f + __expf(-x));
}

static __device__ __forceinline__ uint32_t smem_u32(const void* p) {
    uint32_t a;
    asm("{ .reg .u64 t; cvta.to.shared.u64 t, %1; cvt.u32.u64 %0, t; }" : "=r"(a) : "l"(p));
    return a;
}
#define SW64(o)  ((o) ^ (((o) >> 3) & 0x30))

#define LDSM_X4(r0, r1, r2, r3, addr) \
    asm volatile("ldmatrix.sync.aligned.m8n8.x4.shared.b16 {%0,%1,%2,%3}, [%4];" \
        : "=r"(r0), "=r"(r1), "=r"(r2), "=r"(r3) : "r"(addr))

#define MMA16816F16(c, a, b) \
    asm volatile("mma.sync.aligned.m16n8k16.row.col.f32.f16.f16.f32 " \
        "{%0,%1,%2,%3}, {%4,%5,%6,%7}, {%8,%9}, {%0,%1,%2,%3};" \
        : "+f"((c)[0]), "+f"((c)[1]), "+f"((c)[2]), "+f"((c)[3]) \
        : "r"((a)[0]), "r"((a)[1]), "r"((a)[2]), "r"((a)[3]), \
          "r"((b)[0]), "r"((b)[1]))

// ============================================================
// K1: fused  (a) W_out -> fp16 convert+pad   [blocks 0..1823]
//            (b) g_init = graph @ W_g2e^T + b_g2e  (direct write,
//                tiles 64x16, full K=2048)   [blocks 1824..2079]
// ============================================================
__global__ __launch_bounds__(256) void k_projwcvt(const float* __restrict__ A,
                                                  const float* __restrict__ W,
                                                  const float* __restrict__ bg2e,
                                                  const float* __restrict__ Wout) {
    if (blockIdx.x < WCVT_BLOCKS) {
        int i = blockIdx.x * 256 + threadIdx.x;
        int v = i >> 5, k = i & 31;
        float val = (v < Vdim) ? Wout[v * 32 + k] : 0.f;
        g_wcv[(size_t)v * 32 + k] = __float2half_rn(val);
        return;
    }
    __shared__ __align__(16) float As[32][64];
    __shared__ __align__(16) float Bs[32][16];
    const int pb = blockIdx.x - WCVT_BLOCKS;           // 0..255
    const int m0 = (pb >> 4) * 64, n0 = (pb & 15) * 16;
    const int tid = threadIdx.x;
    const int tx = tid & 15, ty = tid >> 4;            // out: col tx, rows ty*4..+3
    const int r = tid & 63, h = tid >> 6;              // A loader
    const int rb = tid & 15, hb = (tid >> 4) & 7;      // B loader (tid<128)

    const float* Ap = A + (size_t)(m0 + r) * Gdim;
    const float* Wp = W + (size_t)(n0 + rb) * Gdim;

    unsigned long long acc0 = 0ull, acc1 = 0ull;

    for (int kc = 0; kc < Gdim; kc += 32) {
#pragma unroll
        for (int i = 0; i < 2; i++) {
            int seg = h + i * 4;
            float4 v = *(const float4*)(Ap + kc + seg * 4);
            As[seg * 4 + 0][r] = v.x; As[seg * 4 + 1][r] = v.y;
            As[seg * 4 + 2][r] = v.z; As[seg * 4 + 3][r] = v.w;
        }
        if (tid < 128) {
            float4 v = *(const float4*)(Wp + kc + hb * 4);
            Bs[hb * 4 + 0][rb] = v.x; Bs[hb * 4 + 1][rb] = v.y;
            Bs[hb * 4 + 2][rb] = v.z; Bs[hb * 4 + 3][rb] = v.w;
        }
        __syncthreads();
#pragma unroll 8
        for (int k = 0; k < 32; k++) {
            ulonglong2 a = *(const ulonglong2*)&As[k][ty * 4];
            float bv = Bs[k][tx];
            unsigned long long bd = pk2(bv, bv);
            acc0 = fma2(a.x, bd, acc0);
            acc1 = fma2(a.y, bd, acc1);
        }
        __syncthreads();
    }
    const float bias = bg2e[n0 + tx];
    float2 v0 = up2(acc0), v1 = up2(acc1);
    int mbase = m0 + ty * 4;
    g_init[(mbase + 0) * Edim + n0 + tx] = v0.x + bias;
    g_init[(mbase + 1) * Edim + n0 + tx] = v0.y + bias;
    g_init[(mbase + 2) * Edim + n0 + tx] = v1.x + bias;
    g_init[(mbase + 3) * Edim + n0 + tx] = v1.y + bias;
}

// ============================================================
// K2: g_gx0 = x @ W_ih0^T + (b_ih0 + b_hh0), x gathered.
//     M-tile 32 (576 CTAs for occupancy), N=128, K=256.
// ============================================================
__global__ __launch_bounds__(256) void k_gx(const int* __restrict__ sent,
                                            const float* __restrict__ emb,
                                            const float* __restrict__ Wih0,
                                            const float* __restrict__ bih0,
                                            const float* __restrict__ bhh0) {
    __shared__ __align__(16) float As[32][32];
    __shared__ __align__(16) float Bs[32][128];
    const int tid = threadIdx.x;
    const int m0 = blockIdx.x * 32;
    const int tx = tid & 15, ty = tid >> 4;        // out: cols tx+j*16, rows ty*2..+1

    const int r = tid & 31, h = tid >> 5;          // A loader: row r, k seg h
    const int m = m0 + r;
    const int b = m / Sdim, s = m - b * Sdim;
    const float* Ap = (s == 0) ? (g_init + (size_t)b * Edim)
                               : (emb + (size_t)sent[b * Tdim + (s - 1)] * Edim);
    const int rb = tid & 127, hb = tid >> 7;       // B loader
    const float* Bp = Wih0 + (size_t)rb * Edim;

    unsigned long long acc[8];
#pragma unroll
    for (int j = 0; j < 8; j++) acc[j] = 0ull;

    for (int kc = 0; kc < 256; kc += 32) {
        {
            float4 v = *(const float4*)(Ap + kc + h * 4);
            As[h * 4 + 0][r] = v.x; As[h * 4 + 1][r] = v.y;
            As[h * 4 + 2][r] = v.z; As[h * 4 + 3][r] = v.w;
        }
#pragma unroll
        for (int i = 0; i < 4; i++) {
            int seg = i * 2 + hb;
            float4 v = *(const float4*)(Bp + kc + seg * 4);
            Bs[seg * 4 + 0][rb] = v.x; Bs[seg * 4 + 1][rb] = v.y;
            Bs[seg * 4 + 2][rb] = v.z; Bs[seg * 4 + 3][rb] = v.w;
        }
        __syncthreads();
#pragma unroll 8
        for (int k = 0; k < 32; k++) {
            unsigned long long a = *(const unsigned long long*)&As[k][ty * 2];
#pragma unroll
            for (int j = 0; j < 8; j++) {
                float bv = Bs[k][tx + j * 16];
                acc[j] = fma2(a, pk2(bv, bv), acc[j]);
            }
        }
        __syncthreads();
    }
#pragma unroll
    for (int j = 0; j < 8; j++) {
        int n = tx + j * 16;
        float bias = bih0[n] + bhh0[n];
        float2 v = up2(acc[j]);
        int mm = m0 + ty * 2;
        g_gx0[mm * G4 + n] = v.x + bias;
        g_gx0[(mm + 1) * G4 + n] = v.y + bias;
    }
}

// ============================================================
// K3: fused 2-layer LSTM, 18 steps. 1 batch row per warp,
//     256 thr/block, 128 blocks. Emits h2 as fp16 rows (32/row).
// ============================================================
__global__ __launch_bounds__(256) void k_lstm(const float* __restrict__ Whh0,
                                              const float* __restrict__ Wih1,
                                              const float* __restrict__ Whh1,
                                              const float* __restrict__ bih1,
                                              const float* __restrict__ bhh1) {
    __shared__ __align__(16) float W0[32 * 128];   // [k][j][q]
    __shared__ __align__(16) float Wi1[32 * 128];
    __shared__ __align__(16) float Wh1[32 * 128];
    const int tid = threadIdx.x;

    for (int idx = tid; idx < 4096; idx += 256) {
        int k = idx >> 7, rem = idx & 127, j = rem >> 2, q = rem & 3;
        int src = (q * 32 + j) * 32 + k;
        W0[idx]  = Whh0[src];
        Wi1[idx] = Wih1[src];
        Wh1[idx] = Whh1[src];
    }
    __syncthreads();

    const int wid = tid >> 5, j = tid & 31;
    const int brow = blockIdx.x * 8 + wid;

    float b1q[4];
#pragma unroll
    for (int q = 0; q < 4; q++) b1q[q] = bih1[q * 32 + j] + bhh1[q * 32 + j];

    float hA = 0.f, cA = 0.f, hB = 0.f, cB = 0.f;

    float pre[4];
    {
        int m = brow * Sdim;
#pragma unroll
        for (int q = 0; q < 4; q++) pre[q] = g_gx0[m * G4 + q * 32 + j];
    }

    for (int s = 0; s < Sdim; s++) {
        float gl[4];
#pragma unroll
        for (int q = 0; q < 4; q++) gl[q] = pre[q];
        if (s < Sdim - 1) {
            int m = brow * Sdim + s + 1;
#pragma unroll
            for (int q = 0; q < 4; q++) pre[q] = g_gx0[m * G4 + q * 32 + j];
        }
        // layer 0
#pragma unroll
        for (int k = 0; k < 32; k++) {
            float4 w = *(const float4*)&W0[k * 128 + j * 4];
            float h0 = __shfl_sync(0xffffffffu, hA, k);
            gl[0] += w.x * h0; gl[1] += w.y * h0;
            gl[2] += w.z * h0; gl[3] += w.w * h0;
        }
        {
            float ci = sigf(gl[0]), cf = sigf(gl[1]);
            float cg = tanhf(gl[2]), co = sigf(gl[3]);
            cA = cf * cA + ci * cg;
            hA = co * tanhf(cA);
        }
        // layer 1
        float G[4];
#pragma unroll
        for (int q = 0; q < 4; q++) G[q] = b1q[q];
#pragma unroll
        for (int k = 0; k < 32; k++) {
            float4 wi = *(const float4*)&Wi1[k * 128 + j * 4];
            float4 wh = *(const float4*)&Wh1[k * 128 + j * 4];
            float a0 = __shfl_sync(0xffffffffu, hA, k);
            float p0 = __shfl_sync(0xffffffffu, hB, k);
            G[0] += wi.x * a0 + wh.x * p0; G[1] += wi.y * a0 + wh.y * p0;
            G[2] += wi.z * a0 + wh.z * p0; G[3] += wi.w * a0 + wh.w * p0;
        }
        {
            float ci = sigf(G[0]), cf = sigf(G[1]);
            float cg = tanhf(G[2]), co = sigf(G[3]);
            cB = cf * cB + ci * cg;
            hB = co * tanhf(cB);
            g_h2cv[(size_t)(brow * Sdim + s) * 32 + j] = __float2half_rn(hB);
        }
    }
}

// ============================================================
// K4: mma.sync fp16 GEMM  out[18432, 14463] = h2 @ Wout^T + bias
//     CTA tile 128x128, 8 warps (4M x 2N), warp tile 32x64, K=32.
//     Single fp16 product (error ~1.2e-4). Single-pass epilogue
//     via smem (pitch 136 -> conflict-free both directions).
// ============================================================
#define EPI_PITCH 136
#define K4_SMEM (128 * EPI_PITCH * 4)   // 69632; staging (16KB) overlays

__global__ __launch_bounds__(256, 2) void k_out_mma(const float* __restrict__ bout,
                                                    float* __restrict__ out) {
    extern __shared__ __align__(1024) char sm[];
    __half* As = (__half*)sm;                 // 8 KB: 128 rows x 64B, SW64
    __half* Bs = (__half*)(sm + 8192);        // 8 KB: 128 rows x 64B, SW64
    float*  epi = (float*)sm;                 // overlay, 128 x 136 floats

    const int tid = threadIdx.x;
    const int wid = tid >> 5, lane = tid & 31;
    const int n0 = blockIdx.x * 128;
    const int m0 = blockIdx.y * 128;

    // ---- stage A and B (512 int4 each; 2 per thread) ----
    const int4* Ag = (const int4*)(g_h2cv + (size_t)m0 * 32);
    const int4* Bg = (const int4*)(g_wcv + (size_t)n0 * 32);
#pragma unroll
    for (int it = 0; it < 2; it++) {
        int idx = tid + it * 256;
        int row = idx >> 2, u = idx & 3;
        uint32_t off = (uint32_t)(row * 64 + u * 16);
        *(int4*)((char*)As + SW64(off)) = Ag[idx];
        *(int4*)((char*)Bs + SW64(off)) = Bg[idx];
    }

    float bias_r[4];
#pragma unroll
    for (int c = 0; c < 4; c++) {
        int col = n0 + c * 32 + lane;
        bias_r[c] = (col < Vdim) ? bout[col] : 0.f;
    }
    __syncthreads();

    const uint32_t As_u = smem_u32(As);
    const uint32_t Bs_u = smem_u32(Bs);

    const int mwarp = (wid & 3) * 32;
    const int nwarp = (wid >> 2) * 64;
    const int rowa = lane & 15;
    const int sega = lane >> 4;

    float acc[2][8][4];
#pragma unroll
    for (int mf = 0; mf < 2; mf++)
#pragma unroll
        for (int j = 0; j < 8; j++)
#pragma unroll
            for (int q = 0; q < 4; q++) acc[mf][j][q] = 0.f;

#pragma unroll
    for (int p = 0; p < 2; p++) {                 // two k16 steps (K=32)
        uint32_t a[2][4];
#pragma unroll
        for (int mf = 0; mf < 2; mf++) {
            uint32_t off = (uint32_t)((mwarp + mf * 16 + rowa) * 64 + p * 32 + sega * 16);
            LDSM_X4(a[mf][0], a[mf][1], a[mf][2], a[mf][3], As_u + SW64(off));
        }
        uint32_t bfr[8][2];
#pragma unroll
        for (int nb = 0; nb < 4; nb++) {
            uint32_t r0, r1, r2, r3;
            uint32_t off = (uint32_t)((nwarp + nb * 16 + rowa) * 64 + p * 32 + sega * 16);
            LDSM_X4(r0, r1, r2, r3, Bs_u + SW64(off));
            bfr[nb * 2][0] = r0;     bfr[nb * 2][1] = r2;
            bfr[nb * 2 + 1][0] = r1; bfr[nb * 2 + 1][1] = r3;
        }
#pragma unroll
        for (int mf = 0; mf < 2; mf++)
#pragma unroll
            for (int j = 0; j < 8; j++)
                MMA16816F16(acc[mf][j], a[mf], bfr[j]);
    }

    // ---- single-pass epilogue: all accs -> smem, then coalesced stores ----
    __syncthreads();          // staging reads complete; overlay is safe
#pragma unroll
    for (int mf = 0; mf < 2; mf++)
#pragma unroll
        for (int j = 0; j < 8; j++) {
            int colb = nwarp + j * 8 + (lane & 3) * 2;
            int r0 = mwarp + mf * 16 + (lane >> 2);
            *(float2*)&epi[r0 * EPI_PITCH + colb] =
                make_float2(acc[mf][j][0], acc[mf][j][1]);
            *(float2*)&epi[(r0 + 8) * EPI_PITCH + colb] =
                make_float2(acc[mf][j][2], acc[mf][j][3]);
        }
    __syncthreads();

    const int rbase = wid * 16;
#pragma unroll
    for (int rr = 0; rr < 16; rr++) {
        size_t gro = (size_t)(m0 + rbase + rr) * Vdim + n0;
#pragma unroll
        for (int c = 0; c < 4; c++) {
            int col = c * 32 + lane;
            if (n0 + col < Vdim)
                out[gro + col] = epi[(rbase + rr) * EPI_PITCH + col] + bias_r[c];
        }
    }
}

// ============================================================
extern "C" void kernel_launch(void* const* d_in, const int* in_sizes, int n_in,
                              void* d_out, int out_size) {
    const float* graph = (const float*)d_in[0];
    const int*   sent  = (const int*)d_in[1];
    const float* Wg2e  = (const float*)d_in[2];
    const float* bg2e  = (const float*)d_in[3];
    const float* emb   = (const float*)d_in[4];
    const float* Wih0  = (const float*)d_in[5];
    const float* Whh0  = (const float*)d_in[6];
    const float* bih0  = (const float*)d_in[7];
    const float* bhh0  = (const float*)d_in[8];
    const float* Wih1  = (const float*)d_in[9];
    const float* Whh1  = (const float*)d_in[10];
    const float* bih1  = (const float*)d_in[11];
    const float* bhh1  = (const float*)d_in[12];
    const float* Wout  = (const float*)d_in[13];
    const float* bout  = (const float*)d_in[14];
    float* out = (float*)d_out;

    cudaFuncSetAttribute(k_out_mma, cudaFuncAttributeMaxDynamicSharedMemorySize,
                         K4_SMEM);

    k_projwcvt<<<WCVT_BLOCKS + 256, 256>>>(graph, Wg2e, bg2e, Wout);
    k_gx<<<576, 256>>>(sent, emb, Wih0, bih0, bhh0);
    k_lstm<<<128, 256>>>(Whh0, Wih1, Whh1, bih1, bhh1);
    k_out_mma<<<dim3(113, 144), 256, K4_SMEM>>>(bout, out);
}

// round 8
// speedup vs baseline: 1.0845x; 1.0845x over previous
#include <cuda_runtime.h>
#include <cuda_fp16.h>
#include <cstdint>

#define Bsz 1024
#define Gdim 2048
#define Edim 256
#define Hdim 32
#define Vdim 14463
#define Vpad 14592   // 114 * 128
#define Tdim 18
#define Sdim 18      // last step's output is dropped
#define G4  128      // 4*H
#define Mtot (Bsz * Sdim)   // 18432
#define WCVT_BLOCKS 1824    // Vpad*32/256

// ---- scratch (no cudaMalloc allowed) ----
__device__ float g_init[Bsz * Edim];                       // graph projection
__device__ float g_gx0[Bsz * Sdim * G4];                   // L0 input-gates precompute
__device__ __align__(16) __half g_h2cv[Mtot * 32];         // h2 rows: fp16, 32/row
__device__ __align__(16) __half g_wcv[(size_t)Vpad * 32];  // Wout rows: fp16, 32/row

// ================= packed f32x2 helpers =================
static __device__ __forceinline__ unsigned long long pk2(float lo, float hi) {
    unsigned long long r;
    asm("mov.b64 %0, {%1,%2};" : "=l"(r) : "f"(lo), "f"(hi));
    return r;
}
static __device__ __forceinline__ unsigned long long fma2(unsigned long long a,
                                                          unsigned long long b,
                                                          unsigned long long c) {
    unsigned long long d;
    asm("fma.rn.f32x2 %0, %1, %2, %3;" : "=l"(d) : "l"(a), "l"(b), "l"(c));
    return d;
}
static __device__ __forceinline__ float2 up2(unsigned long long v) {
    float2 f;
    asm("mov.b64 {%0,%1}, %2;" : "=f"(f.x), "=f"(f.y) : "l"(v));
    return f;
}
static __device__ __forceinline__ float sigf(float x) {
    return 1.0f / (1.0f + __expf(-x));
}

static __device__ __forceinline__ uint32_t smem_u32(const void* p) {
    uint32_t a;
    asm("{ .reg .u64 t; cvta.to.shared.u64 t, %1; cvt.u32.u64 %0, t; }" : "=r"(a) : "l"(p));
    return a;
}
#define SW64(o)  ((o) ^ (((o) >> 3) & 0x30))

#define LDSM_X4(r0, r1, r2, r3, addr) \
    asm volatile("ldmatrix.sync.aligned.m8n8.x4.shared.b16 {%0,%1,%2,%3}, [%4];" \
        : "=r"(r0), "=r"(r1), "=r"(r2), "=r"(r3) : "r"(addr))

#define MMA16816F16(c, a, b) \
    asm volatile("mma.sync.aligned.m16n8k16.row.col.f32.f16.f16.f32 " \
        "{%0,%1,%2,%3}, {%4,%5,%6,%7}, {%8,%9}, {%0,%1,%2,%3};" \
        : "+f"((c)[0]), "+f"((c)[1]), "+f"((c)[2]), "+f"((c)[3]) \
        : "r"((a)[0]), "r"((a)[1]), "r"((a)[2]), "r"((a)[3]), \
          "r"((b)[0]), "r"((b)[1]))

// ============================================================
// K1: fused  (a) W_out -> fp16 convert+pad   [blocks 0..1823]
//            (b) g_init = graph @ W_g2e^T + b_g2e  (direct write,
//                tiles 64x16, full K=2048)   [blocks 1824..2079]
// ============================================================
__global__ __launch_bounds__(256) void k_projwcvt(const float* __restrict__ A,
                                                  const float* __restrict__ W,
                                                  const float* __restrict__ bg2e,
                                                  const float* __restrict__ Wout) {
    if (blockIdx.x < WCVT_BLOCKS) {
        int i = blockIdx.x * 256 + threadIdx.x;
        int v = i >> 5, k = i & 31;
        float val = (v < Vdim) ? Wout[v * 32 + k] : 0.f;
        g_wcv[(size_t)v * 32 + k] = __float2half_rn(val);
        return;
    }
    __shared__ __align__(16) float As[32][64];
    __shared__ __align__(16) float Bs[32][16];
    const int pb = blockIdx.x - WCVT_BLOCKS;           // 0..255
    const int m0 = (pb >> 4) * 64, n0 = (pb & 15) * 16;
    const int tid = threadIdx.x;
    const int tx = tid & 15, ty = tid >> 4;            // out: col tx, rows ty*4..+3
    const int r = tid & 63, h = tid >> 6;              // A loader
    const int rb = tid & 15, hb = (tid >> 4) & 7;      // B loader (tid<128)

    const float* Ap = A + (size_t)(m0 + r) * Gdim;
    const float* Wp = W + (size_t)(n0 + rb) * Gdim;

    unsigned long long acc0 = 0ull, acc1 = 0ull;

    for (int kc = 0; kc < Gdim; kc += 32) {
#pragma unroll
        for (int i = 0; i < 2; i++) {
            int seg = h + i * 4;
            float4 v = *(const float4*)(Ap + kc + seg * 4);
            As[seg * 4 + 0][r] = v.x; As[seg * 4 + 1][r] = v.y;
            As[seg * 4 + 2][r] = v.z; As[seg * 4 + 3][r] = v.w;
        }
        if (tid < 128) {
            float4 v = *(const float4*)(Wp + kc + hb * 4);
            Bs[hb * 4 + 0][rb] = v.x; Bs[hb * 4 + 1][rb] = v.y;
            Bs[hb * 4 + 2][rb] = v.z; Bs[hb * 4 + 3][rb] = v.w;
        }
        __syncthreads();
#pragma unroll 8
        for (int k = 0; k < 32; k++) {
            ulonglong2 a = *(const ulonglong2*)&As[k][ty * 4];
            float bv = Bs[k][tx];
            unsigned long long bd = pk2(bv, bv);
            acc0 = fma2(a.x, bd, acc0);
            acc1 = fma2(a.y, bd, acc1);
        }
        __syncthreads();
    }
    const float bias = bg2e[n0 + tx];
    float2 v0 = up2(acc0), v1 = up2(acc1);
    int mbase = m0 + ty * 4;
    g_init[(mbase + 0) * Edim + n0 + tx] = v0.x + bias;
    g_init[(mbase + 1) * Edim + n0 + tx] = v0.y + bias;
    g_init[(mbase + 2) * Edim + n0 + tx] = v1.x + bias;
    g_init[(mbase + 3) * Edim + n0 + tx] = v1.y + bias;
}

// ============================================================
// K2: g_gx0 = x @ W_ih0^T + (b_ih0 + b_hh0), x gathered.
//     M-tile 32 (576 CTAs for occupancy), N=128, K=256.
// ============================================================
__global__ __launch_bounds__(256) void k_gx(const int* __restrict__ sent,
                                            const float* __restrict__ emb,
                                            const float* __restrict__ Wih0,
                                            const float* __restrict__ bih0,
                                            const float* __restrict__ bhh0) {
    __shared__ __align__(16) float As[32][32];
    __shared__ __align__(16) float Bs[32][128];
    const int tid = threadIdx.x;
    const int m0 = blockIdx.x * 32;
    const int tx = tid & 15, ty = tid >> 4;        // out: cols tx+j*16, rows ty*2..+1

    const int r = tid & 31, h = tid >> 5;          // A loader: row r, k seg h
    const int m = m0 + r;
    const int b = m / Sdim, s = m - b * Sdim;
    const float* Ap = (s == 0) ? (g_init + (size_t)b * Edim)
                               : (emb + (size_t)sent[b * Tdim + (s - 1)] * Edim);
    const int rb = tid & 127, hb = tid >> 7;       // B loader
    const float* Bp = Wih0 + (size_t)rb * Edim;

    unsigned long long acc[8];
#pragma unroll
    for (int j = 0; j < 8; j++) acc[j] = 0ull;

    for (int kc = 0; kc < 256; kc += 32) {
        {
            float4 v = *(const float4*)(Ap + kc + h * 4);
            As[h * 4 + 0][r] = v.x; As[h * 4 + 1][r] = v.y;
            As[h * 4 + 2][r] = v.z; As[h * 4 + 3][r] = v.w;
        }
#pragma unroll
        for (int i = 0; i < 4; i++) {
            int seg = i * 2 + hb;
            float4 v = *(const float4*)(Bp + kc + seg * 4);
            Bs[seg * 4 + 0][rb] = v.x; Bs[seg * 4 + 1][rb] = v.y;
            Bs[seg * 4 + 2][rb] = v.z; Bs[seg * 4 + 3][rb] = v.w;
        }
        __syncthreads();
#pragma unroll 8
        for (int k = 0; k < 32; k++) {
            unsigned long long a = *(const unsigned long long*)&As[k][ty * 2];
#pragma unroll
            for (int j = 0; j < 8; j++) {
                float bv = Bs[k][tx + j * 16];
                acc[j] = fma2(a, pk2(bv, bv), acc[j]);
            }
        }
        __syncthreads();
    }
#pragma unroll
    for (int j = 0; j < 8; j++) {
        int n = tx + j * 16;
        float bias = bih0[n] + bhh0[n];
        float2 v = up2(acc[j]);
        int mm = m0 + ty * 2;
        g_gx0[mm * G4 + n] = v.x + bias;
        g_gx0[(mm + 1) * G4 + n] = v.y + bias;
    }
}

// ============================================================
// K3: fused 2-layer LSTM, 18 steps. 1 batch row per warp,
//     256 thr/block, 128 blocks. Emits h2 as fp16 rows (32/row).
// ============================================================
__global__ __launch_bounds__(256) void k_lstm(const float* __restrict__ Whh0,
                                              const float* __restrict__ Wih1,
                                              const float* __restrict__ Whh1,
                                              const float* __restrict__ bih1,
                                              const float* __restrict__ bhh1) {
    __shared__ __align__(16) float W0[32 * 128];   // [k][j][q]
    __shared__ __align__(16) float Wi1[32 * 128];
    __shared__ __align__(16) float Wh1[32 * 128];
    const int tid = threadIdx.x;

    for (int idx = tid; idx < 4096; idx += 256) {
        int k = idx >> 7, rem = idx & 127, j = rem >> 2, q = rem & 3;
        int src = (q * 32 + j) * 32 + k;
        W0[idx]  = Whh0[src];
        Wi1[idx] = Wih1[src];
        Wh1[idx] = Whh1[src];
    }
    __syncthreads();

    const int wid = tid >> 5, j = tid & 31;
    const int brow = blockIdx.x * 8 + wid;

    float b1q[4];
#pragma unroll
    for (int q = 0; q < 4; q++) b1q[q] = bih1[q * 32 + j] + bhh1[q * 32 + j];

    float hA = 0.f, cA = 0.f, hB = 0.f, cB = 0.f;

    float pre[4];
    {
        int m = brow * Sdim;
#pragma unroll
        for (int q = 0; q < 4; q++) pre[q] = g_gx0[m * G4 + q * 32 + j];
    }

    for (int s = 0; s < Sdim; s++) {
        float gl[4];
#pragma unroll
        for (int q = 0; q < 4; q++) gl[q] = pre[q];
        if (s < Sdim - 1) {
            int m = brow * Sdim + s + 1;
#pragma unroll
            for (int q = 0; q < 4; q++) pre[q] = g_gx0[m * G4 + q * 32 + j];
        }
        // layer 0
#pragma unroll
        for (int k = 0; k < 32; k++) {
            float4 w = *(const float4*)&W0[k * 128 + j * 4];
            float h0 = __shfl_sync(0xffffffffu, hA, k);
            gl[0] += w.x * h0; gl[1] += w.y * h0;
            gl[2] += w.z * h0; gl[3] += w.w * h0;
        }
        {
            float ci = sigf(gl[0]), cf = sigf(gl[1]);
            float cg = tanhf(gl[2]), co = sigf(gl[3]);
            cA = cf * cA + ci * cg;
            hA = co * tanhf(cA);
        }
        // layer 1
        float G[4];
#pragma unroll
        for (int q = 0; q < 4; q++) G[q] = b1q[q];
#pragma unroll
        for (int k = 0; k < 32; k++) {
            float4 wi = *(const float4*)&Wi1[k * 128 + j * 4];
            float4 wh = *(const float4*)&Wh1[k * 128 + j * 4];
            float a0 = __shfl_sync(0xffffffffu, hA, k);
            float p0 = __shfl_sync(0xffffffffu, hB, k);
            G[0] += wi.x * a0 + wh.x * p0; G[1] += wi.y * a0 + wh.y * p0;
            G[2] += wi.z * a0 + wh.z * p0; G[3] += wi.w * a0 + wh.w * p0;
        }
        {
            float ci = sigf(G[0]), cf = sigf(G[1]);
            float cg = tanhf(G[2]), co = sigf(G[3]);
            cB = cf * cB + ci * cg;
            hB = co * tanhf(cB);
            g_h2cv[(size_t)(brow * Sdim + s) * 32 + j] = __float2half_rn(hB);
        }
    }
}

// ============================================================
// K4: mma.sync fp16 GEMM  out[18432, 14463] = h2 @ Wout^T + bias
//     CTA tile 128x128, 8 warps (4M x 2N), warp tile 32x64, K=32.
//     Single fp16 product (error ~1.2e-4). Single-pass epilogue
//     via smem (pitch 136 -> conflict-free both directions).
// ============================================================
#define EPI_PITCH 136
#define K4_SMEM (128 * EPI_PITCH * 4)   // 69632; staging (16KB) overlays

__global__ __launch_bounds__(256, 2) void k_out_mma(const float* __restrict__ bout,
                                                    float* __restrict__ out) {
    extern __shared__ __align__(1024) char sm[];
    __half* As = (__half*)sm;                 // 8 KB: 128 rows x 64B, SW64
    __half* Bs = (__half*)(sm + 8192);        // 8 KB: 128 rows x 64B, SW64
    float*  epi = (float*)sm;                 // overlay, 128 x 136 floats

    const int tid = threadIdx.x;
    const int wid = tid >> 5, lane = tid & 31;
    const int n0 = blockIdx.x * 128;
    const int m0 = blockIdx.y * 128;

    // ---- stage A and B (512 int4 each; 2 per thread) ----
    const int4* Ag = (const int4*)(g_h2cv + (size_t)m0 * 32);
    const int4* Bg = (const int4*)(g_wcv + (size_t)n0 * 32);
#pragma unroll
    for (int it = 0; it < 2; it++) {
        int idx = tid + it * 256;
        int row = idx >> 2, u = idx & 3;
        uint32_t off = (uint32_t)(row * 64 + u * 16);
        *(int4*)((char*)As + SW64(off)) = Ag[idx];
        *(int4*)((char*)Bs + SW64(off)) = Bg[idx];
    }

    float bias_r[4];
#pragma unroll
    for (int c = 0; c < 4; c++) {
        int col = n0 + c * 32 + lane;
        bias_r[c] = (col < Vdim) ? bout[col] : 0.f;
    }
    __syncthreads();

    const uint32_t As_u = smem_u32(As);
    const uint32_t Bs_u = smem_u32(Bs);

    const int mwarp = (wid & 3) * 32;
    const int nwarp = (wid >> 2) * 64;
    const int rowa = lane & 15;
    const int sega = lane >> 4;

    float acc[2][8][4];
#pragma unroll
    for (int mf = 0; mf < 2; mf++)
#pragma unroll
        for (int j = 0; j < 8; j++)
#pragma unroll
            for (int q = 0; q < 4; q++) acc[mf][j][q] = 0.f;

#pragma unroll
    for (int p = 0; p < 2; p++) {                 // two k16 steps (K=32)
        uint32_t a[2][4];
#pragma unroll
        for (int mf = 0; mf < 2; mf++) {
            uint32_t off = (uint32_t)((mwarp + mf * 16 + rowa) * 64 + p * 32 + sega * 16);
            LDSM_X4(a[mf][0], a[mf][1], a[mf][2], a[mf][3], As_u + SW64(off));
        }
        uint32_t bfr[8][2];
#pragma unroll
        for (int nb = 0; nb < 4; nb++) {
            uint32_t r0, r1, r2, r3;
            uint32_t off = (uint32_t)((nwarp + nb * 16 + rowa) * 64 + p * 32 + sega * 16);
            LDSM_X4(r0, r1, r2, r3, Bs_u + SW64(off));
            bfr[nb * 2][0] = r0;     bfr[nb * 2][1] = r2;
            bfr[nb * 2 + 1][0] = r1; bfr[nb * 2 + 1][1] = r3;
        }
#pragma unroll
        for (int mf = 0; mf < 2; mf++)
#pragma unroll
            for (int j = 0; j < 8; j++)
                MMA16816F16(acc[mf][j], a[mf], bfr[j]);
    }

    // ---- single-pass epilogue: all accs -> smem, then coalesced stores ----
    __syncthreads();          // staging reads complete; overlay is safe
#pragma unroll
    for (int mf = 0; mf < 2; mf++)
#pragma unroll
        for (int j = 0; j < 8; j++) {
            int colb = nwarp + j * 8 + (lane & 3) * 2;
            int r0 = mwarp + mf * 16 + (lane >> 2);
            *(float2*)&epi[r0 * EPI_PITCH + colb] =
                make_float2(acc[mf][j][0], acc[mf][j][1]);
            *(float2*)&epi[(r0 + 8) * EPI_PITCH + colb] =
                make_float2(acc[mf][j][2], acc[mf][j][3]);
        }
    __syncthreads();

    const int rbase = wid * 16;
#pragma unroll
    for (int rr = 0; rr < 16; rr++) {
        size_t gro = (size_t)(m0 + rbase + rr) * Vdim + n0;
#pragma unroll
        for (int c = 0; c < 4; c++) {
            int col = c * 32 + lane;
            if (n0 + col < Vdim)
                out[gro + col] = epi[(rbase + rr) * EPI_PITCH + col] + bias_r[c];
        }
    }
}

// ============================================================
extern "C" void kernel_launch(void* const* d_in, const int* in_sizes, int n_in,
                              void* d_out, int out_size) {
    const float* graph = (const float*)d_in[0];
    const int*   sent  = (const int*)d_in[1];
    const float* Wg2e  = (const float*)d_in[2];
    const float* bg2e  = (const float*)d_in[3];
    const float* emb   = (const float*)d_in[4];
    const float* Wih0  = (const float*)d_in[5];
    const float* Whh0  = (const float*)d_in[6];
    const float* bih0  = (const float*)d_in[7];
    const float* bhh0  = (const float*)d_in[8];
    const float* Wih1  = (const float*)d_in[9];
    const float* Whh1  = (const float*)d_in[10];
    const float* bih1  = (const float*)d_in[11];
    const float* bhh1  = (const float*)d_in[12];
    const float* Wout  = (const float*)d_in[13];
    const float* bout  = (const float*)d_in[14];
    float* out = (float*)d_out;

    cudaFuncSetAttribute(k_out_mma, cudaFuncAttributeMaxDynamicSharedMemorySize,
                         K4_SMEM);

    k_projwcvt<<<WCVT_BLOCKS + 256, 256>>>(graph, Wg2e, bg2e, Wout);
    k_gx<<<576, 256>>>(sent, emb, Wih0, bih0, bhh0);
    k_lstm<<<128, 256>>>(Whh0, Wih1, Whh1, bih1, bhh1);
    k_out_mma<<<dim3(113, 144), 256, K4_SMEM>>>(bout, out);
}

// round 9
// speedup vs baseline: 1.5968x; 1.4724x over previous
#include <cuda_runtime.h>
#include <cuda_fp16.h>
#include <cstdint>

#define Bsz 1024
#define Gdim 2048
#define Edim 256
#define Hdim 32
#define Vdim 14463
#define Vpad 14592   // 114 * 128
#define Tdim 18
#define Sdim 18      // last step's output is dropped
#define G4  128      // 4*H
#define Mtot (Bsz * Sdim)   // 18432

// ---- scratch (no cudaMalloc allowed) ----
__device__ float g_init[Bsz * Edim];                       // graph projection
__device__ float g_gx0[Bsz * Sdim * G4];                   // L0 input-gates precompute
__device__ __align__(16) __half g_h2cv[Mtot * 32];         // h2 rows: fp16, 32/row
__device__ __align__(16) __half g_wcv[(size_t)Vpad * 32];  // Wout rows: fp16, 32/row

// ================= packed f32x2 helpers =================
static __device__ __forceinline__ unsigned long long pk2(float lo, float hi) {
    unsigned long long r;
    asm("mov.b64 %0, {%1,%2};" : "=l"(r) : "f"(lo), "f"(hi));
    return r;
}
static __device__ __forceinline__ unsigned long long fma2(unsigned long long a,
                                                          unsigned long long b,
                                                          unsigned long long c) {
    unsigned long long d;
    asm("fma.rn.f32x2 %0, %1, %2, %3;" : "=l"(d) : "l"(a), "l"(b), "l"(c));
    return d;
}
static __device__ __forceinline__ float2 up2(unsigned long long v) {
    float2 f;
    asm("mov.b64 {%0,%1}, %2;" : "=f"(f.x), "=f"(f.y) : "l"(v));
    return f;
}
static __device__ __forceinline__ float sigf(float x) {
    return 1.0f / (1.0f + __expf(-x));
}

static __device__ __forceinline__ uint32_t smem_u32(const void* p) {
    uint32_t a;
    asm("{ .reg .u64 t; cvta.to.shared.u64 t, %1; cvt.u32.u64 %0, t; }" : "=r"(a) : "l"(p));
    return a;
}
#define SW64(o)  ((o) ^ (((o) >> 3) & 0x30))

#define LDSM_X4(r0, r1, r2, r3, addr) \
    asm volatile("ldmatrix.sync.aligned.m8n8.x4.shared.b16 {%0,%1,%2,%3}, [%4];" \
        : "=r"(r0), "=r"(r1), "=r"(r2), "=r"(r3) : "r"(addr))

#define MMA16816F16(c, a, b) \
    asm volatile("mma.sync.aligned.m16n8k16.row.col.f32.f16.f16.f32 " \
        "{%0,%1,%2,%3}, {%4,%5,%6,%7}, {%8,%9}, {%0,%1,%2,%3};" \
        : "+f"((c)[0]), "+f"((c)[1]), "+f"((c)[2]), "+f"((c)[3]) \
        : "r"((a)[0]), "r"((a)[1]), "r"((a)[2]), "r"((a)[3]), \
          "r"((b)[0]), "r"((b)[1]))

// ============================================================
// K0: init g_init with broadcast bias (split-K GEMM accumulates into it)
// ============================================================
__global__ void k_initbias(const float* __restrict__ b_g2e) {
    int i = blockIdx.x * blockDim.x + threadIdx.x;
    if (i < Bsz * Edim) g_init[i] = b_g2e[i & (Edim - 1)];
}

// ============================================================
// K0b: convert+pad W_out to fp16 (32/row)
// ============================================================
__global__ void k_wcvt(const float* __restrict__ Wout) {
    int i = blockIdx.x * blockDim.x + threadIdx.x;
    if (i >= Vpad * 32) return;
    int v = i >> 5, k = i & 31;
    float val = (v < Vdim) ? Wout[v * 32 + k] : 0.f;
    g_wcv[(size_t)v * 32 + k] = __float2half_rn(val);
}

// ============================================================
// K1: g_init += graph_embedding @ W_g2e^T  (split-K=8, f32x2)  [R6 form]
// ============================================================
__global__ __launch_bounds__(256) void k_proj(const float* __restrict__ A,
                                              const float* __restrict__ W) {
    __shared__ __align__(16) float As[32][64];
    __shared__ __align__(16) float Bs[32][64];
    const int tid = threadIdx.x;
    const int m0 = blockIdx.y * 64;
    const int n0 = blockIdx.x * 64;
    const int kbase = blockIdx.z * 256;

    const int tx = tid & 15, ty = tid >> 4;
    const int r = tid & 63, h = tid >> 6;

    const float* Ap = A + (size_t)(m0 + r) * Gdim + kbase;
    const float* Wp = W + (size_t)(n0 + r) * Gdim + kbase;

    unsigned long long acc[4][2];
#pragma unroll
    for (int j = 0; j < 4; j++) { acc[j][0] = 0ull; acc[j][1] = 0ull; }

    for (int kc = 0; kc < 256; kc += 32) {
#pragma unroll
        for (int i = 0; i < 2; i++) {
            int seg = h + i * 4;
            float4 va = *(const float4*)(Ap + kc + seg * 4);
            As[seg * 4 + 0][r] = va.x; As[seg * 4 + 1][r] = va.y;
            As[seg * 4 + 2][r] = va.z; As[seg * 4 + 3][r] = va.w;
            float4 vb = *(const float4*)(Wp + kc + seg * 4);
            Bs[seg * 4 + 0][r] = vb.x; Bs[seg * 4 + 1][r] = vb.y;
            Bs[seg * 4 + 2][r] = vb.z; Bs[seg * 4 + 3][r] = vb.w;
        }
        __syncthreads();
#pragma unroll 8
        for (int k = 0; k < 32; k++) {
            ulonglong2 a = *(const ulonglong2*)&As[k][ty * 4];
#pragma unroll
            for (int j = 0; j < 4; j++) {
                float bv = Bs[k][tx + j * 16];
                unsigned long long bd = pk2(bv, bv);
                acc[j][0] = fma2(a.x, bd, acc[j][0]);
                acc[j][1] = fma2(a.y, bd, acc[j][1]);
            }
        }
        __syncthreads();
    }
#pragma unroll
    for (int j = 0; j < 4; j++) {
        int n = n0 + tx + j * 16;
#pragma unroll
        for (int p = 0; p < 2; p++) {
            float2 v = up2(acc[j][p]);
            int m = m0 + ty * 4 + p * 2;
            atomicAdd(&g_init[m * Edim + n], v.x);
            atomicAdd(&g_init[(m + 1) * Edim + n], v.y);
        }
    }
}

// ============================================================
// K2: g_gx0 = x @ W_ih0^T + (b_ih0 + b_hh0), x gathered  [R6 64-tile form]
// ============================================================
__global__ __launch_bounds__(256) void k_gx(const int* __restrict__ sent,
                                            const float* __restrict__ emb,
                                            const float* __restrict__ Wih0,
                                            const float* __restrict__ bih0,
                                            const float* __restrict__ bhh0) {
    __shared__ __align__(16) float As[32][64];
    __shared__ __align__(16) float Bs[32][128];
    const int tid = threadIdx.x;
    const int m0 = blockIdx.x * 64;
    const int tx = tid & 15, ty = tid >> 4;

    const int r = tid & 63;
    const int ha = tid >> 6;
    const int m = m0 + r;
    const int b = m / Sdim, s = m - b * Sdim;
    const float* Ap = (s == 0) ? (g_init + (size_t)b * Edim)
                               : (emb + (size_t)sent[b * Tdim + (s - 1)] * Edim);
    const int rb = tid & 127;
    const int hb = tid >> 7;
    const float* Bp = Wih0 + (size_t)rb * Edim;

    unsigned long long acc[8][2];
#pragma unroll
    for (int j = 0; j < 8; j++) { acc[j][0] = 0ull; acc[j][1] = 0ull; }

    for (int kc = 0; kc < 256; kc += 32) {
#pragma unroll
        for (int i = 0; i < 2; i++) {
            int seg = ha + i * 4;
            float4 v = *(const float4*)(Ap + kc + seg * 4);
            As[seg * 4 + 0][r] = v.x; As[seg * 4 + 1][r] = v.y;
            As[seg * 4 + 2][r] = v.z; As[seg * 4 + 3][r] = v.w;
        }
#pragma unroll
        for (int i = 0; i < 4; i++) {
            int seg = i * 2 + hb;
            float4 v = *(const float4*)(Bp + kc + seg * 4);
            Bs[seg * 4 + 0][rb] = v.x; Bs[seg * 4 + 1][rb] = v.y;
            Bs[seg * 4 + 2][rb] = v.z; Bs[seg * 4 + 3][rb] = v.w;
        }
        __syncthreads();
#pragma unroll 8
        for (int k = 0; k < 32; k++) {
            ulonglong2 a = *(const ulonglong2*)&As[k][ty * 4];
#pragma unroll
            for (int j = 0; j < 8; j++) {
                float bv = Bs[k][tx + j * 16];
                unsigned long long bd = pk2(bv, bv);
                acc[j][0] = fma2(a.x, bd, acc[j][0]);
                acc[j][1] = fma2(a.y, bd, acc[j][1]);
            }
        }
        __syncthreads();
    }
#pragma unroll
    for (int j = 0; j < 8; j++) {
        int n = tx + j * 16;
        float bias = bih0[n] + bhh0[n];
#pragma unroll
        for (int p = 0; p < 2; p++) {
            float2 v = up2(acc[j][p]);
            int mm = m0 + ty * 4 + p * 2;
            g_gx0[mm * G4 + n] = v.x + bias;
            g_gx0[(mm + 1) * G4 + n] = v.y + bias;
        }
    }
}

// ============================================================
// K3: fused 2-layer LSTM, 18 steps. 1 batch row per warp,
//     256 thr/block, 128 blocks. Emits h2 as fp16 rows (32/row).
// ============================================================
__global__ __launch_bounds__(256) void k_lstm(const float* __restrict__ Whh0,
                                              const float* __restrict__ Wih1,
                                              const float* __restrict__ Whh1,
                                              const float* __restrict__ bih1,
                                              const float* __restrict__ bhh1) {
    __shared__ __align__(16) float W0[32 * 128];   // [k][j][q]
    __shared__ __align__(16) float Wi1[32 * 128];
    __shared__ __align__(16) float Wh1[32 * 128];
    const int tid = threadIdx.x;

    for (int idx = tid; idx < 4096; idx += 256) {
        int k = idx >> 7, rem = idx & 127, j = rem >> 2, q = rem & 3;
        int src = (q * 32 + j) * 32 + k;
        W0[idx]  = Whh0[src];
        Wi1[idx] = Wih1[src];
        Wh1[idx] = Whh1[src];
    }
    __syncthreads();

    const int wid = tid >> 5, j = tid & 31;
    const int brow = blockIdx.x * 8 + wid;

    float b1q[4];
#pragma unroll
    for (int q = 0; q < 4; q++) b1q[q] = bih1[q * 32 + j] + bhh1[q * 32 + j];

    float hA = 0.f, cA = 0.f, hB = 0.f, cB = 0.f;

    float pre[4];
    {
        int m = brow * Sdim;
#pragma unroll
        for (int q = 0; q < 4; q++) pre[q] = g_gx0[m * G4 + q * 32 + j];
    }

    for (int s = 0; s < Sdim; s++) {
        float gl[4];
#pragma unroll
        for (int q = 0; q < 4; q++) gl[q] = pre[q];
        if (s < Sdim - 1) {
            int m = brow * Sdim + s + 1;
#pragma unroll
            for (int q = 0; q < 4; q++) pre[q] = g_gx0[m * G4 + q * 32 + j];
        }
        // layer 0
#pragma unroll
        for (int k = 0; k < 32; k++) {
            float4 w = *(const float4*)&W0[k * 128 + j * 4];
            float h0 = __shfl_sync(0xffffffffu, hA, k);
            gl[0] += w.x * h0; gl[1] += w.y * h0;
            gl[2] += w.z * h0; gl[3] += w.w * h0;
        }
        {
            float ci = sigf(gl[0]), cf = sigf(gl[1]);
            float cg = tanhf(gl[2]), co = sigf(gl[3]);
            cA = cf * cA + ci * cg;
            hA = co * tanhf(cA);
        }
        // layer 1
        float G[4];
#pragma unroll
        for (int q = 0; q < 4; q++) G[q] = b1q[q];
#pragma unroll
        for (int k = 0; k < 32; k++) {
            float4 wi = *(const float4*)&Wi1[k * 128 + j * 4];
            float4 wh = *(const float4*)&Wh1[k * 128 + j * 4];
            float a0 = __shfl_sync(0xffffffffu, hA, k);
            float p0 = __shfl_sync(0xffffffffu, hB, k);
            G[0] += wi.x * a0 + wh.x * p0; G[1] += wi.y * a0 + wh.y * p0;
            G[2] += wi.z * a0 + wh.z * p0; G[3] += wi.w * a0 + wh.w * p0;
        }
        {
            float ci = sigf(G[0]), cf = sigf(G[1]);
            float cg = tanhf(G[2]), co = sigf(G[3]);
            cB = cf * cB + ci * cg;
            hB = co * tanhf(cB);
            g_h2cv[(size_t)(brow * Sdim + s) * 32 + j] = __float2half_rn(hB);
        }
    }
}

// ============================================================
// K4: mma.sync fp16 GEMM  out[18432, 14463] = h2 @ Wout^T + bias
//     [R8 form, measured 223.6us] CTA tile 128x128, 8 warps, K=32.
//     Single-pass epilogue via smem (pitch 136, conflict-free).
// ============================================================
#define EPI_PITCH 136
#define K4_SMEM (128 * EPI_PITCH * 4)   // 69632; staging (16KB) overlays

__global__ __launch_bounds__(256, 2) void k_out_mma(const float* __restrict__ bout,
                                                    float* __restrict__ out) {
    extern __shared__ __align__(1024) char sm[];
    __half* As = (__half*)sm;                 // 8 KB: 128 rows x 64B, SW64
    __half* Bs = (__half*)(sm + 8192);        // 8 KB: 128 rows x 64B, SW64
    float*  epi = (float*)sm;                 // overlay, 128 x 136 floats

    const int tid = threadIdx.x;
    const int wid = tid >> 5, lane = tid & 31;
    const int n0 = blockIdx.x * 128;
    const int m0 = blockIdx.y * 128;

    // ---- stage A and B (512 int4 each; 2 per thread) ----
    const int4* Ag = (const int4*)(g_h2cv + (size_t)m0 * 32);
    const int4* Bg = (const int4*)(g_wcv + (size_t)n0 * 32);
#pragma unroll
    for (int it = 0; it < 2; it++) {
        int idx = tid + it * 256;
        int row = idx >> 2, u = idx & 3;
        uint32_t off = (uint32_t)(row * 64 + u * 16);
        *(int4*)((char*)As + SW64(off)) = Ag[idx];
        *(int4*)((char*)Bs + SW64(off)) = Bg[idx];
    }

    float bias_r[4];
#pragma unroll
    for (int c = 0; c < 4; c++) {
        int col = n0 + c * 32 + lane;
        bias_r[c] = (col < Vdim) ? bout[col] : 0.f;
    }
    __syncthreads();

    const uint32_t As_u = smem_u32(As);
    const uint32_t Bs_u = smem_u32(Bs);

    const int mwarp = (wid & 3) * 32;
    const int nwarp = (wid >> 2) * 64;
    const int rowa = lane & 15;
    const int sega = lane >> 4;

    float acc[2][8][4];
#pragma unroll
    for (int mf = 0; mf < 2; mf++)
#pragma unroll
        for (int j = 0; j < 8; j++)
#pragma unroll
            for (int q = 0; q < 4; q++) acc[mf][j][q] = 0.f;

#pragma unroll
    for (int p = 0; p < 2; p++) {                 // two k16 steps (K=32)
        uint32_t a[2][4];
#pragma unroll
        for (int mf = 0; mf < 2; mf++) {
            uint32_t off = (uint32_t)((mwarp + mf * 16 + rowa) * 64 + p * 32 + sega * 16);
            LDSM_X4(a[mf][0], a[mf][1], a[mf][2], a[mf][3], As_u + SW64(off));
        }
        uint32_t bfr[8][2];
#pragma unroll
        for (int nb = 0; nb < 4; nb++) {
            uint32_t r0, r1, r2, r3;
            uint32_t off = (uint32_t)((nwarp + nb * 16 + rowa) * 64 + p * 32 + sega * 16);
            LDSM_X4(r0, r1, r2, r3, Bs_u + SW64(off));
            bfr[nb * 2][0] = r0;     bfr[nb * 2][1] = r2;
            bfr[nb * 2 + 1][0] = r1; bfr[nb * 2 + 1][1] = r3;
        }
#pragma unroll
        for (int mf = 0; mf < 2; mf++)
#pragma unroll
            for (int j = 0; j < 8; j++)
                MMA16816F16(acc[mf][j], a[mf], bfr[j]);
    }

    // ---- single-pass epilogue: all accs -> smem, then coalesced stores ----
    __syncthreads();          // staging reads complete; overlay is safe
#pragma unroll
    for (int mf = 0; mf < 2; mf++)
#pragma unroll
        for (int j = 0; j < 8; j++) {
            int colb = nwarp + j * 8 + (lane & 3) * 2;
            int r0 = mwarp + mf * 16 + (lane >> 2);
            *(float2*)&epi[r0 * EPI_PITCH + colb] =
                make_float2(acc[mf][j][0], acc[mf][j][1]);
            *(float2*)&epi[(r0 + 8) * EPI_PITCH + colb] =
                make_float2(acc[mf][j][2], acc[mf][j][3]);
        }
    __syncthreads();

    const int rbase = wid * 16;
#pragma unroll
    for (int rr = 0; rr < 16; rr++) {
        size_t gro = (size_t)(m0 + rbase + rr) * Vdim + n0;
#pragma unroll
        for (int c = 0; c < 4; c++) {
            int col = c * 32 + lane;
            if (n0 + col < Vdim)
                out[gro + col] = epi[(rbase + rr) * EPI_PITCH + col] + bias_r[c];
        }
    }
}

// ============================================================
extern "C" void kernel_launch(void* const* d_in, const int* in_sizes, int n_in,
                              void* d_out, int out_size) {
    const float* graph = (const float*)d_in[0];
    const int*   sent  = (const int*)d_in[1];
    const float* Wg2e  = (const float*)d_in[2];
    const float* bg2e  = (const float*)d_in[3];
    const float* emb   = (const float*)d_in[4];
    const float* Wih0  = (const float*)d_in[5];
    const float* Whh0  = (const float*)d_in[6];
    const float* bih0  = (const float*)d_in[7];
    const float* bhh0  = (const float*)d_in[8];
    const float* Wih1  = (const float*)d_in[9];
    const float* Whh1  = (const float*)d_in[10];
    const float* bih1  = (const float*)d_in[11];
    const float* bhh1  = (const float*)d_in[12];
    const float* Wout  = (const float*)d_in[13];
    const float* bout  = (const float*)d_in[14];
    float* out = (float*)d_out;

    cudaFuncSetAttribute(k_out_mma, cudaFuncAttributeMaxDynamicSharedMemorySize,
                         K4_SMEM);

    k_initbias<<<512, 512>>>(bg2e);
    k_wcvt<<<(Vpad * 32 + 255) / 256, 256>>>(Wout);
    k_proj<<<dim3(4, 16, 8), 256>>>(graph, Wg2e);
    k_gx<<<288, 256>>>(sent, emb, Wih0, bih0, bhh0);
    k_lstm<<<128, 256>>>(Whh0, Wih1, Whh1, bih1, bhh1);
    k_out_mma<<<dim3(113, 144), 256, K4_SMEM>>>(bout, out);
}